// round 1
// baseline (speedup 1.0000x reference)
#include <cuda_runtime.h>

// Problem constants
#define NZ_COLS 512          // DIM_IN
#define MULV    128
#define NZT     64           // z-tile for main kernel
#define WCH     8            // w-slices per CTA in main kernel
#define K2_ZT   32           // z-tile for scalar kernel

// PW constants
#define PW_SS 0.0625f
#define PW_VV 0.03608439182435161f        // 1/(16*sqrt(3))
#define PW_SV 0.0078125f                  // sqrt(3)/128/sqrt(3) = 1/128

// Transposed copy of w_sv: g_wt[w][u][v] = w_sv[u][v][w]   (8.4 MB scratch)
__device__ float g_wt[128 * 128 * 128];

// ---------------------------------------------------------------------------
// Prologue: transpose w_sv[u,v,w] -> g_wt[w,u,v] so per-w slices are [u][v]
// contiguous. For each u we transpose the (v,w) 128x128 matrix.
// ---------------------------------------------------------------------------
__global__ void transpose_wsv_kernel(const float* __restrict__ wsv) {
    __shared__ float tile[32][33];
    const int u  = blockIdx.z;
    const int v0 = blockIdx.y * 32;
    const int w0 = blockIdx.x * 32;
    const float* src = wsv + (size_t)u * 16384;
#pragma unroll
    for (int j = threadIdx.y; j < 32; j += 8)
        tile[j][threadIdx.x] = src[(size_t)(v0 + j) * 128 + (w0 + threadIdx.x)];
    __syncthreads();
#pragma unroll
    for (int j = threadIdx.y; j < 32; j += 8)
        g_wt[(size_t)(w0 + j) * 16384 + (size_t)u * 128 + (v0 + threadIdx.x)] =
            tile[threadIdx.x][j];
}

// ---------------------------------------------------------------------------
// Main kernel: fused  t[z,v,w] = sum_u xs[z,u]*w_sv[u,v,w]
//                     out_v[z,w,i] = PW_SV * sum_v t[z,v,w]*xv[z,v,i]
// CTA: 64 z-rows x 8 consecutive w. 128 threads, 8z x 8v register tile.
// smem: xs tile [64][128] (32KB) + W slice [128][128] (64KB) = 96KB -> 2 CTA/SM
// ---------------------------------------------------------------------------
__global__ __launch_bounds__(128) void sv_main_kernel(
    const float* __restrict__ x, float* __restrict__ out)
{
    extern __shared__ float smem[];
    float* xs_s = smem;              // [64][128]
    float* ws_s = smem + NZT * 128;  // [128][128]  (u-major, v contiguous)

    const int tid = threadIdx.x;
    const int tx  = tid & 15;        // v-group  (16 groups of 8 v)
    const int ty  = tid >> 4;        // z-group  (8 groups of 8 z)
    const int z0    = blockIdx.x * NZT;
    const int wbase = blockIdx.y * WCH;

    // Load xs tile (coalesced float4)
    for (int i = tid; i < NZT * 128 / 4; i += 128) {
        int r = i >> 5;              // z row within tile
        int c = (i & 31) << 2;       // column
        *(float4*)(xs_s + r * 128 + c) =
            *(const float4*)(x + (size_t)(z0 + r) * NZ_COLS + c);
    }

    const int zb = ty * 8;
    const int vb = tx * 8;

    for (int wi = 0; wi < WCH; ++wi) {
        const int w = wbase + wi;
        __syncthreads();             // prev-iter smem reads done / xs load done
        {
            const float* wt = g_wt + (size_t)w * 16384;
            for (int i = tid; i < 16384 / 4; i += 128)
                *(float4*)(ws_s + i * 4) = *(const float4*)(wt + i * 4);
        }
        __syncthreads();

        // GEMM: acc[j][k] = t[z0+zb+j, vb+k] for this w
        float acc[8][8];
#pragma unroll
        for (int j = 0; j < 8; ++j)
#pragma unroll
            for (int k = 0; k < 8; ++k) acc[j][k] = 0.f;

#pragma unroll 8
        for (int u = 0; u < 128; ++u) {
            float4 b0 = *(const float4*)(ws_s + u * 128 + vb);
            float4 b1 = *(const float4*)(ws_s + u * 128 + vb + 4);
            float bb[8] = {b0.x, b0.y, b0.z, b0.w, b1.x, b1.y, b1.z, b1.w};
#pragma unroll
            for (int j = 0; j < 8; ++j) {
                float a = xs_s[(zb + j) * 128 + u];
#pragma unroll
                for (int k = 0; k < 8; ++k) acc[j][k] += a * bb[k];
            }
        }

        // Epilogue: reduce over v with xv, then across the 16 v-lanes.
#pragma unroll
        for (int j = 0; j < 8; ++j) {
            const int z = z0 + zb + j;
            // xv[z, vb..vb+7, 0..2] = 24 consecutive floats (aligned)
            const float4* pv =
                (const float4*)(x + (size_t)z * NZ_COLS + MULV + vb * 3);
            float4 q0 = pv[0], q1 = pv[1], q2 = pv[2];
            float4 q3 = pv[3], q4 = pv[4], q5 = pv[5];
            float vv[24] = {q0.x, q0.y, q0.z, q0.w, q1.x, q1.y, q1.z, q1.w,
                            q2.x, q2.y, q2.z, q2.w, q3.x, q3.y, q3.z, q3.w,
                            q4.x, q4.y, q4.z, q4.w, q5.x, q5.y, q5.z, q5.w};
            float o0 = 0.f, o1 = 0.f, o2 = 0.f;
#pragma unroll
            for (int k = 0; k < 8; ++k) {
                o0 += acc[j][k] * vv[k * 3 + 0];
                o1 += acc[j][k] * vv[k * 3 + 1];
                o2 += acc[j][k] * vv[k * 3 + 2];
            }
            // butterfly over tx (lane bits 0..3): full sum lands in all lanes
#pragma unroll
            for (int m = 8; m >= 1; m >>= 1) {
                o0 += __shfl_xor_sync(0xffffffffu, o0, m);
                o1 += __shfl_xor_sync(0xffffffffu, o1, m);
                o2 += __shfl_xor_sync(0xffffffffu, o2, m);
            }
            if (tx == 0) {
                float* po = out + (size_t)z * NZ_COLS + MULV + w * 3;
                po[0] = PW_SV * o0;
                po[1] = PW_SV * o1;
                po[2] = PW_SV * o2;
            }
        }
    }
}

// ---------------------------------------------------------------------------
// Scalar kernel: out_s[z,u] = PW_SS*xs[z,u]*(w_ss @ xs[z])_u
//                           + PW_VV*sum_i xv[z,u,i]*(w_vv @ xv[z,:,i])_u
// CTA: 32 z rows, all 128 u. 512 threads, thread tile 2z x 4u.
// smem: x tile [32][512] (64KB) + transposed weights 2x[128][132] (135KB)
// ---------------------------------------------------------------------------
__global__ __launch_bounds__(512) void scalar_kernel(
    const float* __restrict__ x, const float* __restrict__ w_ss,
    const float* __restrict__ w_vv, float* __restrict__ out)
{
    extern __shared__ float smem[];
    float* xt   = smem;                    // [32][512]
    float* wsst = smem + K2_ZT * NZ_COLS;  // [128][132]  (v-major, u contiguous)
    float* wvvt = wsst + 128 * 132;        // [128][132]

    const int tid = threadIdx.x;
    const int z0  = blockIdx.x * K2_ZT;

    for (int i = tid; i < K2_ZT * NZ_COLS / 4; i += 512)
        ((float4*)xt)[i] = ((const float4*)(x + (size_t)z0 * NZ_COLS))[i];
    for (int i = tid; i < 16384; i += 512) {
        int r = i >> 7, c = i & 127;       // w[r][c] -> wt[c][r]
        wsst[c * 132 + r] = w_ss[i];
        wvvt[c * 132 + r] = w_vv[i];
    }
    __syncthreads();

    const int tx = tid & 31;               // u-group (32 groups of 4 u)
    const int ty = tid >> 5;               // z-group (16 groups of 2 z)
    const int u  = tx * 4;
    const int zl = ty * 2;

    float ass[2][4], av0[2][4], av1[2][4], av2[2][4];
#pragma unroll
    for (int j = 0; j < 2; ++j)
#pragma unroll
        for (int k = 0; k < 4; ++k) {
            ass[j][k] = 0.f; av0[j][k] = 0.f; av1[j][k] = 0.f; av2[j][k] = 0.f;
        }

#pragma unroll 4
    for (int v = 0; v < 128; ++v) {
        float4 ws4 = *(const float4*)(wsst + v * 132 + u);
        float4 wv4 = *(const float4*)(wvvt + v * 132 + u);
        float wsa[4] = {ws4.x, ws4.y, ws4.z, ws4.w};
        float wva[4] = {wv4.x, wv4.y, wv4.z, wv4.w};
#pragma unroll
        for (int jz = 0; jz < 2; ++jz) {
            const float* row = xt + (zl + jz) * NZ_COLS;
            float xsv = row[v];
            float a0 = row[MULV + v * 3 + 0];
            float a1 = row[MULV + v * 3 + 1];
            float a2 = row[MULV + v * 3 + 2];
#pragma unroll
            for (int k = 0; k < 4; ++k) {
                ass[jz][k] += wsa[k] * xsv;
                av0[jz][k] += wva[k] * a0;
                av1[jz][k] += wva[k] * a1;
                av2[jz][k] += wva[k] * a2;
            }
        }
    }

#pragma unroll
    for (int jz = 0; jz < 2; ++jz) {
        const int z = z0 + zl + jz;
        const float* row = xt + (zl + jz) * NZ_COLS;
        float res[4];
#pragma unroll
        for (int k = 0; k < 4; ++k) {
            int uu = u + k;
            float xsu = row[uu];
            float b0 = row[MULV + uu * 3 + 0];
            float b1 = row[MULV + uu * 3 + 1];
            float b2 = row[MULV + uu * 3 + 2];
            res[k] = PW_SS * xsu * ass[jz][k] +
                     PW_VV * (b0 * av0[jz][k] + b1 * av1[jz][k] + b2 * av2[jz][k]);
        }
        float4 r4 = {res[0], res[1], res[2], res[3]};
        *(float4*)(out + (size_t)z * NZ_COLS + u) = r4;
    }
}

// ---------------------------------------------------------------------------
extern "C" void kernel_launch(void* const* d_in, const int* in_sizes, int n_in,
                              void* d_out, int out_size)
{
    const float* x    = (const float*)d_in[0];
    const float* w_ss = (const float*)d_in[1];
    const float* w_sv = (const float*)d_in[2];
    const float* w_vv = (const float*)d_in[3];
    float* out = (float*)d_out;

    const int n = in_sizes[0] / NZ_COLS;   // 8192

    const int main_smem = (NZT * 128 + 128 * 128) * 4;          // 96 KB
    const int k2_smem   = (K2_ZT * NZ_COLS + 2 * 128 * 132) * 4; // ~196 KB

    cudaFuncSetAttribute(sv_main_kernel,
                         cudaFuncAttributeMaxDynamicSharedMemorySize, main_smem);
    cudaFuncSetAttribute(scalar_kernel,
                         cudaFuncAttributeMaxDynamicSharedMemorySize, k2_smem);

    transpose_wsv_kernel<<<dim3(4, 4, 128), dim3(32, 8)>>>(w_sv);
    scalar_kernel<<<n / K2_ZT, 512, k2_smem>>>(x, w_ss, w_vv, out);
    sv_main_kernel<<<dim3(n / NZT, MULV / WCH), 128, main_smem>>>(x, out);
}